// round 2
// baseline (speedup 1.0000x reference)
#include <cuda_runtime.h>
#include <math.h>

// Problem constants
#define BB    16
#define CC    64
#define HWSZ  4096         // 64*64
#define NPIX  65536        // BB*HWSZ
#define KK    1024
#define DD    64
#define NEL   4194304      // BB*CC*HWSZ

#define TILE_P 128
#define CHUNK  128
#define GATHER_BLOCKS 16384   // NEL / 256

// Device scratch (no allocations allowed)
__device__ int   g_idx[NPIX];
__device__ float g_counts[KK];
__device__ float g_cnorm[KK];
__device__ float g_xnorm[NPIX];
__device__ float g_part[GATHER_BLOCKS];

// ---------------------------------------------------------------------------
// Kernel 1a: codebook norms (XLA-style: rounded mul then rounded add, seq d)
//            + zero histogram
// ---------------------------------------------------------------------------
__global__ void prep_kernel(const float* __restrict__ cb) {
    int t = blockIdx.x * blockDim.x + threadIdx.x;
    if (t < KK) {
        float s = 0.f;
        #pragma unroll
        for (int d = 0; d < DD; d++) {
            float v = cb[t * DD + d];
            s = __fadd_rn(s, __fmul_rn(v, v));
        }
        g_cnorm[t]  = s;
        g_counts[t] = 0.f;
    }
}

// ---------------------------------------------------------------------------
// Kernel 1b: per-pixel ||x||^2 (XLA-style sequential mul+add, d ascending)
// ---------------------------------------------------------------------------
__global__ void xnorm_kernel(const float* __restrict__ in) {
    int n  = blockIdx.x * 256 + threadIdx.x;   // pixel id
    int b  = n >> 12;
    int hw = n & 4095;
    const float* p = in + (size_t)b * CC * HWSZ + hw;
    float s = 0.f;
    #pragma unroll
    for (int d = 0; d < DD; d++) {
        float v = p[(size_t)d * HWSZ];
        s = __fadd_rn(s, __fmul_rn(v, v));
    }
    g_xnorm[n] = s;
}

// ---------------------------------------------------------------------------
// Kernel 2: argmin over codes (tiled fp32 GEMM-style), + histogram
// Replicates reference score: d = fl(fl(ns + cn) - fl(2*dot)),
// dot = sequential-k fp32 FMA chain (Eigen-style).
// smem layout (floats):
//   xs  [64][128]  @ 0       (8192)
//   cs  [64][132]  @ 8192    (8448, padded)
//   cns [128]      @ 16640
// total 16768 floats = 67072 bytes (dynamic)
// ---------------------------------------------------------------------------
extern __shared__ float smem[];

__global__ void __launch_bounds__(256, 2)
argmin_kernel(const float* __restrict__ in, const float* __restrict__ cb) {
    float* xs  = smem;
    float* cs  = smem + 8192;
    float* cns = smem + 8192 + 64 * 132;

    const int tid = threadIdx.x;
    const int tx  = tid & 15;   // pixel group: pixels tx*8 .. tx*8+7
    const int ty  = tid >> 4;   // code group:  codes  ty*8 .. ty*8+7 (within chunk)

    const int n0  = blockIdx.x * TILE_P;   // tile never crosses a batch boundary
    const int b   = n0 >> 12;
    const int hw0 = n0 & 4095;
    const float* xin = in + (size_t)b * CC * HWSZ + hw0;

    // load x tile: xs[d][p] = in[b, d, hw0+p]  (coalesced)
    for (int i = tid; i < 64 * 128; i += 256) {
        int d = i >> 7, p = i & 127;
        xs[d * 128 + p] = xin[(size_t)d * HWSZ + p];
    }

    // per-thread pixel norms
    float nsv[8];
    #pragma unroll
    for (int i = 0; i < 8; i++) nsv[i] = g_xnorm[n0 + tx * 8 + i];

    float bd[8];
    int   bi[8];
    #pragma unroll
    for (int i = 0; i < 8; i++) { bd[i] = 3.4e38f; bi[i] = 0; }

    for (int kc = 0; kc < KK; kc += CHUNK) {
        __syncthreads();
        // load codebook chunk transposed: cs[d][k] = cb[kc+k][d]
        for (int i = tid; i < CHUNK * 64; i += 256) {
            int k = i >> 6, d = i & 63;
            cs[d * 132 + k] = cb[(size_t)(kc + k) * DD + d];
        }
        if (tid < CHUNK) cns[tid] = g_cnorm[kc + tid];
        __syncthreads();

        float acc[8][8];
        #pragma unroll
        for (int i = 0; i < 8; i++)
            #pragma unroll
            for (int j = 0; j < 8; j++) acc[i][j] = 0.f;

        // dot: strictly d-ascending single-accumulator fp32 FMA chain
        #pragma unroll 2
        for (int d = 0; d < 64; d++) {
            const float4 xa  = *reinterpret_cast<const float4*>(&xs[d * 128 + tx * 8]);
            const float4 xb2 = *reinterpret_cast<const float4*>(&xs[d * 128 + tx * 8 + 4]);
            const float4 ca  = *reinterpret_cast<const float4*>(&cs[d * 132 + ty * 8]);
            const float4 cb2 = *reinterpret_cast<const float4*>(&cs[d * 132 + ty * 8 + 4]);
            float xv[8] = {xa.x, xa.y, xa.z, xa.w, xb2.x, xb2.y, xb2.z, xb2.w};
            float cv[8] = {ca.x, ca.y, ca.z, ca.w, cb2.x, cb2.y, cb2.z, cb2.w};
            #pragma unroll
            for (int i = 0; i < 8; i++)
                #pragma unroll
                for (int j = 0; j < 8; j++)
                    acc[i][j] = __fmaf_rn(xv[i], cv[j], acc[i][j]);
        }

        // running min update with reference-exact rounding:
        // s = fl(fl(ns + cn) - fl(2*dot)); ascending k + strict '<' keeps
        // the first-index min within this thread.
        #pragma unroll
        for (int i = 0; i < 8; i++) {
            #pragma unroll
            for (int j = 0; j < 8; j++) {
                float s = __fsub_rn(__fadd_rn(nsv[i], cns[ty * 8 + j]),
                                    __fmul_rn(2.0f, acc[i][j]));
                if (s < bd[i]) { bd[i] = s; bi[i] = kc + ty * 8 + j; }
            }
        }
    }

    // cross-thread (over ty) min reduction, reusing smem
    __syncthreads();
    float* rd = smem;                     // [16][128]
    int*   ri = (int*)(smem + 2048);      // [16][128]
    #pragma unroll
    for (int i = 0; i < 8; i++) {
        rd[ty * 128 + tx * 8 + i] = bd[i];
        ri[ty * 128 + tx * 8 + i] = bi[i];
    }
    __syncthreads();
    if (tid < 128) {
        float best = rd[tid];
        int   bidx = ri[tid];
        // explicit first-index tiebreak (ty order != index order across chunks)
        for (int t = 1; t < 16; t++) {
            float v  = rd[t * 128 + tid];
            int   vi = ri[t * 128 + tid];
            if (v < best || (v == best && vi < bidx)) { best = v; bidx = vi; }
        }
        g_idx[n0 + tid] = bidx;
        atomicAdd(&g_counts[bidx], 1.0f);   // integer-valued float sum: deterministic
    }
}

// ---------------------------------------------------------------------------
// Kernel 3: gather quantized output + per-block loss partial
// ---------------------------------------------------------------------------
__global__ void gather_loss_kernel(const float* __restrict__ in,
                                   const float* __restrict__ cb,
                                   float* __restrict__ outq) {
    const int tid = threadIdx.x;
    const int e   = blockIdx.x * 256 + tid;

    int b  = e >> 18;       // / (64*4096)
    int r  = e & 262143;
    int c  = r >> 12;       // channel
    int hw = r & 4095;
    int idx = g_idx[(b << 12) | hw];

    float x  = in[e];
    float q  = __ldg(&cb[idx * DD + c]);
    float dv = q - x;
    outq[e]  = x + dv;      // straight-through: x + sg(q - x)
    float part = dv * dv;

    // deterministic block reduction
    #pragma unroll
    for (int o = 16; o; o >>= 1)
        part += __shfl_xor_sync(0xffffffffu, part, o);
    __shared__ float ws[8];
    if ((tid & 31) == 0) ws[tid >> 5] = part;
    __syncthreads();
    if (tid == 0) {
        float s = 0.f;
        #pragma unroll
        for (int w = 0; w < 8; w++) s += ws[w];
        g_part[blockIdx.x] = s;
    }
}

// ---------------------------------------------------------------------------
// Kernel 4: finalize loss + perplexity (single block, 1024 threads, deterministic)
// ---------------------------------------------------------------------------
__global__ void finalize_kernel(const float* __restrict__ beta,
                                float* __restrict__ loss_out,
                                float* __restrict__ pp_out) {
    const int t = threadIdx.x;   // 1024 threads

    float ls = 0.f;
    #pragma unroll
    for (int i = 0; i < GATHER_BLOCKS / 1024; i++)
        ls += g_part[t * (GATHER_BLOCKS / 1024) + i];

    float em  = g_counts[t] * (1.0f / (float)NPIX);
    float ent = em * logf(em + 1e-10f);

    #pragma unroll
    for (int o = 16; o; o >>= 1) {
        ls  += __shfl_xor_sync(0xffffffffu, ls, o);
        ent += __shfl_xor_sync(0xffffffffu, ent, o);
    }
    __shared__ float wl[32], we[32];
    if ((t & 31) == 0) { wl[t >> 5] = ls; we[t >> 5] = ent; }
    __syncthreads();
    if (t == 0) {
        float tl = 0.f, te = 0.f;
        #pragma unroll
        for (int w = 0; w < 32; w++) { tl += wl[w]; te += we[w]; }
        float mean = tl / (float)NEL;
        *loss_out = (1.0f + *beta) * 10.0f * mean;   // KLD_SCALE = 10
        *pp_out   = expf(-te);
    }
}

// ---------------------------------------------------------------------------
// Launch
// ---------------------------------------------------------------------------
extern "C" void kernel_launch(void* const* d_in, const int* in_sizes, int n_in,
                              void* d_out, int out_size) {
    const float* in   = nullptr;
    const float* cb   = nullptr;
    const float* beta = nullptr;
    for (int i = 0; i < n_in; i++) {
        if      (in_sizes[i] == NEL)      in   = (const float*)d_in[i];
        else if (in_sizes[i] == KK * DD)  cb   = (const float*)d_in[i];
        else if (in_sizes[i] == 1)        beta = (const float*)d_in[i];
    }

    float* out      = (float*)d_out;
    float* loss_out = out;                     // out[0] = loss
    float* q_out    = out + 1;                 // out[1 .. NEL] = quantized [B,C,H,W]
    float* pp_out   = out + (out_size - 1);    // out[last] = perplexity

    cudaFuncSetAttribute(argmin_kernel,
                         cudaFuncAttributeMaxDynamicSharedMemorySize, 67072);

    prep_kernel<<<(KK + 255) / 256, 256>>>(cb);
    xnorm_kernel<<<NPIX / 256, 256>>>(in);
    argmin_kernel<<<NPIX / TILE_P, 256, 67072>>>(in, cb);
    gather_loss_kernel<<<GATHER_BLOCKS, 256>>>(in, cb, q_out);
    finalize_kernel<<<1, 1024>>>(beta, loss_out, pp_out);
}